// round 16
// baseline (speedup 1.0000x reference)
#include <cuda_runtime.h>
#include <cuda_bf16.h>
#include <cstdint>
#include <math.h>

// ---------------- problem constants ----------------
#define NENT   100000
#define HDIM   128
#define NR2    460
#define TT     4
#define EE     200000
#define SLOPE  0.22916666666666666f
#define NTHR   256
#define MTILE  64

// ---- smem layouts (A: 16KB hi + 16KB lo; W: 32KB hi + 32KB lo) ----
#define PG_A     0
#define PG_W     32768
#define PG_SIZE  98304
#define K3_BTG   0
#define K3_BGA   512
#define K3_BTD   1024
#define K3_SRED  1536
#define K3_A1    4096
#define K3_W     (K3_A1 + 32768)
#define K3_SIZE  (K3_W + 65536)      // 102400 -> 2 CTAs/SM

// ---------------- scratch ----------------
__device__ float g_hA [NENT*HDIM];
__device__ float g_hB [NENT*HDIM];
__device__ float g_CL [NENT*HDIM];          // cur @ Wl2
__device__ float g_HL [NENT*HDIM];          // h   @ Wl1
__device__ float g_HW [NENT*HDIM];
__device__ float g_agg[NENT*HDIM + NENT];   // deg appended -> single memset
__device__ float g_relA[NR2*HDIM];
__device__ float g_relB[NR2*HDIM];
__device__ float g_R1 [NR2*HDIM];
__device__ float g_R2 [NR2*HDIM];
__device__ float g_pre[9][NR2*HDIM];
__device__ unsigned char g_Wpack[17][65536];

__device__ __forceinline__ float sigf(float x) { return 1.0f / (1.0f + __expf(-x)); }

__device__ __forceinline__ uint32_t smem_u32(const void* p) {
    uint32_t a;
    asm("{ .reg .u64 t; cvta.to.shared.u64 t, %1; cvt.u32.u64 %0, t; }" : "=r"(a) : "l"(p));
    return a;
}
__device__ __host__ __forceinline__ uint32_t swz(uint32_t off) {
    return off ^ ((off >> 4) & 0x70);
}
__device__ __forceinline__ void ldsm4(uint32_t* r, uint32_t a) {
    asm volatile("ldmatrix.sync.aligned.m8n8.x4.shared.b16 {%0,%1,%2,%3}, [%4];"
                 : "=r"(r[0]),"=r"(r[1]),"=r"(r[2]),"=r"(r[3]) : "r"(a));
}
__device__ __forceinline__ void ldsm4t(uint32_t* r, uint32_t a) {
    asm volatile("ldmatrix.sync.aligned.m8n8.x4.trans.shared.b16 {%0,%1,%2,%3}, [%4];"
                 : "=r"(r[0]),"=r"(r[1]),"=r"(r[2]),"=r"(r[3]) : "r"(a));
}
__device__ __forceinline__ void mma16816(float* d, const uint32_t* a, uint32_t b0, uint32_t b1) {
    asm volatile("mma.sync.aligned.m16n8k16.row.col.f32.bf16.bf16.f32 "
                 "{%0,%1,%2,%3},{%4,%5,%6,%7},{%8,%9},{%0,%1,%2,%3};"
                 : "+f"(d[0]),"+f"(d[1]),"+f"(d[2]),"+f"(d[3])
                 : "r"(a[0]),"r"(a[1]),"r"(a[2]),"r"(a[3]),"r"(b0),"r"(b1));
}
__device__ __forceinline__ void cp16(uint32_t saddr, const void* gaddr) {
    asm volatile("cp.async.cg.shared.global [%0], [%1], 16;" :: "r"(saddr), "l"(gaddr));
}

// ---------------- weight pack ----------------
__global__ void pack_kernel(const float* __restrict__ Wn1, const float* __restrict__ Wl1,
                            const float* __restrict__ Wn2, const float* __restrict__ Wl2,
                            const float* __restrict__ tgW, const float* __restrict__ gateW,
                            const float* __restrict__ tdW,
                            const float* __restrict__ gWx, const float* __restrict__ gWh) {
    int m = blockIdx.x;
    unsigned char* base = g_Wpack[m];
    for (int idx = threadIdx.x; idx < 16384; idx += blockDim.x) {
        int k = idx >> 7, n = idx & 127;
        float v;
        if      (m == 0) v = Wn1[k * 128 + n];
        else if (m == 1) v = Wl1[k * 128 + n];
        else if (m == 2) v = Wn2[k * 128 + n];
        else if (m == 3) v = Wl2[k * 128 + n];
        else if (m == 4) v = tgW[k * 128 + n];
        else if (m == 5) v = gateW[n * 256 + k];
        else if (m == 6) v = gateW[n * 256 + 128 + k];
        else if (m == 7) v = tdW[n * 128 + k];
        else if (m < 14) {
            int g = (m - 8) >> 1, kt = (m - 8) & 1;
            v = gWx[(g * 128 + n) * 256 + kt * 128 + k];
        } else {
            int g = m - 14;
            v = gWh[(g * 128 + n) * 128 + k];
        }
        __nv_bfloat16 hi = __float2bfloat16(v);
        __nv_bfloat16 lo = __float2bfloat16(v - __bfloat162float(hi));
        uint32_t o = swz((uint32_t)(k * 256 + n * 2));
        *(__nv_bfloat16*)(base + o)         = hi;
        *(__nv_bfloat16*)(base + 32768 + o) = lo;
    }
}

// ---------------- l2norm ----------------
__global__ void l2norm_kernel(const float* __restrict__ in, float* __restrict__ out, int M) {
    int w = (blockIdx.x * blockDim.x + threadIdx.x) >> 5;
    int lane = threadIdx.x & 31;
    if (w >= M) return;
    float4 v = ((const float4*)in)[w*32 + lane];
    float ss = v.x*v.x + v.y*v.y + v.z*v.z + v.w*v.w;
    #pragma unroll
    for (int o = 16; o; o >>= 1) ss += __shfl_xor_sync(0xffffffffu, ss, o);
    float inv = 1.0f / fmaxf(sqrtf(ss), 1e-12f);
    v.x *= inv; v.y *= inv; v.z *= inv; v.w *= inv;
    ((float4*)out)[w*32 + lane] = v;
}

// ---------------- edge gather + vector-atomic scatter ----------------
__global__ void edge_kernel(const int* __restrict__ src, const int* __restrict__ dst,
                            const int* __restrict__ ety, const float* __restrict__ HW,
                            const float* __restrict__ R, float* __restrict__ agg,
                            float* __restrict__ deg, int E, int do_deg) {
    int e = (blockIdx.x * blockDim.x + threadIdx.x) >> 5;
    int lane = threadIdx.x & 31;
    if (e >= E) return;
    int s = __ldg(src + e), d = __ldg(dst + e), r = __ldg(ety + e);
    float4 v  = __ldg(((const float4*)HW) + s*32 + lane);
    float4 rv = __ldg(((const float4*)R)  + r*32 + lane);
    v.x += rv.x; v.y += rv.y; v.z += rv.z; v.w += rv.w;
    float* p = agg + (size_t)d*128 + lane*4;
    asm volatile("red.global.add.v4.f32 [%0], {%1,%2,%3,%4};"
                 :: "l"(p), "f"(v.x), "f"(v.y), "f"(v.z), "f"(v.w) : "memory");
    if (do_deg && lane == 0) atomicAdd(deg + d, 1.0f);
}

// ---------------- staging (64-row tiles) ----------------
__device__ __forceinline__ void stage_A_g(char* smc, int dstOff, const float* A,
                                          int row0, int M, int tid) {
    #pragma unroll
    for (int it = 0; it < 4; it++) {
        int i = tid + it * NTHR;
        int r = i >> 4, c8 = i & 15;
        int gr = row0 + r;
        float4 v0 = make_float4(0.f,0.f,0.f,0.f), v1 = v0;
        if (gr < M) {
            v0 = __ldg(((const float4*)A) + (size_t)gr*32 + c8*2);
            v1 = __ldg(((const float4*)A) + (size_t)gr*32 + c8*2 + 1);
        }
        float f[8] = {v0.x, v0.y, v0.z, v0.w, v1.x, v1.y, v1.z, v1.w};
        __nv_bfloat162 hi[4], lo[4];
        #pragma unroll
        for (int q = 0; q < 4; q++) {
            __nv_bfloat16 hx = __float2bfloat16(f[2*q]);
            __nv_bfloat16 hy = __float2bfloat16(f[2*q+1]);
            hi[q].x = hx; hi[q].y = hy;
            lo[q].x = __float2bfloat16(f[2*q]   - __bfloat162float(hx));
            lo[q].y = __float2bfloat16(f[2*q+1] - __bfloat162float(hy));
        }
        uint32_t off = swz((uint32_t)(r*256 + c8*16));
        *(uint4*)(smc + dstOff + off)         = *(uint4*)hi;
        *(uint4*)(smc + dstOff + 16384 + off) = *(uint4*)lo;
    }
}
__device__ __forceinline__ void stage_W(uint32_t sb, int dstOff, const unsigned char* Wimg, int tid) {
    uint32_t s = sb + dstOff;
    #pragma unroll 2
    for (int i = tid; i < 4096; i += NTHR) cp16(s + i*16, Wimg + (size_t)i*16);
    asm volatile("cp.async.commit_group;");
}
__device__ __forceinline__ float2 readA2(const char* smc, int off, int row, int c) {
    uint32_t o = swz((uint32_t)(row*256 + c*2));
    __nv_bfloat162 h = *(const __nv_bfloat162*)(smc + off + o);
    __nv_bfloat162 l = *(const __nv_bfloat162*)(smc + off + 16384 + o);
    return make_float2(__bfloat162float(h.x) + __bfloat162float(l.x),
                       __bfloat162float(h.y) + __bfloat162float(l.y));
}
// fragments -> smem hi/lo; gsub: subtract gmem fp32 rows
__device__ __forceinline__ void stage_A_r(char* smc, int dstOff, const float hv[2][4][4],
                                          int lid, int wm, int wn,
                                          const float* gsub, int row0, int M) {
    #pragma unroll
    for (int mi = 0; mi < 2; mi++)
        #pragma unroll
        for (int rr = 0; rr < 2; rr++) {
            int row = wm*32 + mi*16 + rr*8 + (lid >> 2);
            int gr = row0 + row;
            bool rv = gsub && (gr < M);
            #pragma unroll
            for (int nj = 0; nj < 4; nj++) {
                int c = wn*32 + nj*8 + (lid & 3)*2;
                float v0 = hv[mi][nj][rr*2], v1 = hv[mi][nj][rr*2+1];
                if (gsub) {
                    float2 s = rv ? *(const float2*)(gsub + (size_t)gr*128 + c)
                                  : make_float2(0.f, 0.f);
                    v0 -= s.x; v1 -= s.y;
                }
                __nv_bfloat16 h0 = __float2bfloat16(v0), h1 = __float2bfloat16(v1);
                __nv_bfloat162 hi2, lo2;
                hi2.x = h0; hi2.y = h1;
                lo2.x = __float2bfloat16(v0 - __bfloat162float(h0));
                lo2.y = __float2bfloat16(v1 - __bfloat162float(h1));
                uint32_t o = swz((uint32_t)(row*256 + c*2));
                *(__nv_bfloat162*)(smc + dstOff + o)         = hi2;
                *(__nv_bfloat162*)(smc + dstOff + 16384 + o) = lo2;
            }
        }
}

// ---------------- mainloop: warp tile 32x32, split-bf16 ----------------
__device__ __forceinline__ void gemm_tile(uint32_t sb, uint32_t aOff, uint32_t wOff,
                                          int lid, int wm, int wn, float acc[2][4][4]) {
    #pragma unroll
    for (int k0 = 0; k0 < 128; k0 += 16) {
        uint32_t aH[2][4], aL[2][4];
        #pragma unroll
        for (int mi = 0; mi < 2; mi++) {
            int row = wm*32 + mi*16 + (lid & 15);
            int col = k0 + ((lid >> 4) << 3);
            uint32_t off = swz((uint32_t)(row*256 + col*2));
            ldsm4(aH[mi], sb + aOff + off);
            ldsm4(aL[mi], sb + aOff + 16384 + off);
        }
        uint32_t bH[2][4], bL[2][4];
        #pragma unroll
        for (int pi = 0; pi < 2; pi++) {
            int krow = k0 + (lid & 15);
            int col  = wn*32 + pi*16 + ((lid >> 4) << 3);
            uint32_t off = swz((uint32_t)(krow*256 + col*2));
            ldsm4t(bH[pi], sb + wOff + off);
            ldsm4t(bL[pi], sb + wOff + 32768 + off);
        }
        #pragma unroll
        for (int mi = 0; mi < 2; mi++)
            #pragma unroll
            for (int nj = 0; nj < 4; nj++) {
                int pi = nj >> 1, o = (nj & 1) * 2;
                mma16816(acc[mi][nj], aH[mi], bH[pi][o], bH[pi][o+1]);
                mma16816(acc[mi][nj], aL[mi], bH[pi][o], bH[pi][o+1]);
                mma16816(acc[mi][nj], aH[mi], bL[pi][o], bL[pi][o+1]);
            }
    }
}
#define ZERO_ACC(acc) { _Pragma("unroll") for (int a_=0;a_<2;a_++) _Pragma("unroll") for (int b_=0;b_<4;b_++) _Pragma("unroll") for (int c_=0;c_<4;c_++) acc[a_][b_][c_]=0.0f; }

__device__ __forceinline__ void write_plain(float* C, int M, int row0, int lid, int wm, int wn,
                                            const float acc[2][4][4]) {
    #pragma unroll
    for (int mi = 0; mi < 2; mi++)
        #pragma unroll
        for (int rr = 0; rr < 2; rr++) {
            int gr = row0 + wm*32 + mi*16 + rr*8 + (lid >> 2);
            if (gr >= M) continue;
            #pragma unroll
            for (int nj = 0; nj < 4; nj++) {
                int c = wn*32 + nj*8 + (lid & 3)*2;
                *(float2*)(C + (size_t)gr*128 + c) =
                    make_float2(acc[mi][nj][rr*2], acc[mi][nj][rr*2+1]);
            }
        }
}

// ---------------- plain GEMM body ----------------
__device__ __forceinline__ void plain_body(const float* A, const unsigned char* Wimg,
                                           float* C, int M, int row0) {
    extern __shared__ char smc[];
    uint32_t sb = smem_u32(smc);
    int tid = threadIdx.x, wid = tid >> 5, lid = tid & 31;
    int wm = wid & 1, wn = wid >> 1;
    stage_W(sb, PG_W, Wimg, tid);
    stage_A_g(smc, PG_A, A, row0, M, tid);
    asm volatile("cp.async.wait_group 0;");
    __syncthreads();
    float acc[2][4][4]; ZERO_ACC(acc);
    gemm_tile(sb, PG_A, PG_W, lid, wm, wn, acc);
    write_plain(C, M, row0, lid, wm, wn, acc);
}

__global__ __launch_bounds__(NTHR, 2) void plain_gemm(
    const float* __restrict__ A, const unsigned char* __restrict__ Wimg,
    float* __restrict__ C, int M) {
    plain_body(A, Wimg, C, M, blockIdx.x * MTILE);
}

// gru_step body: pre[3+prod] = rel @ W(prod)
__device__ __forceinline__ void gru_step_body(const float* rel, const unsigned char* Wp,
                                              float* preBase, int b) {
    int prod = b >> 3, rb = b & 7;
    const unsigned char* W = Wp + (size_t)((prod < 3) ? (8 + 2*prod + 1) : (14 + prod - 3))*65536;
    plain_body(rel, W, preBase + (size_t)(3 + prod)*NR2*HDIM, NR2, rb * MTILE);
}

// XE precompute (once)
__global__ __launch_bounds__(NTHR, 2) void gru_pre(
    const float* __restrict__ emb_rel, const unsigned char* __restrict__ Wp,
    float* __restrict__ preBase) {
    int g = blockIdx.x >> 3, rb = blockIdx.x & 7;
    plain_body(emb_rel, Wp + (size_t)(8 + 2*g)*65536,
               preBase + (size_t)g*NR2*HDIM, NR2, rb * MTILE);
}
// standalone gru_step (pre-loop only)
__global__ __launch_bounds__(NTHR, 2) void gru_step(
    const float* __restrict__ rel, const unsigned char* __restrict__ Wp,
    float* __restrict__ preBase) {
    gru_step_body(rel, Wp, preBase, blockIdx.x);
}

// ---------------- gru_combine body ----------------
__device__ __forceinline__ void gru_combine_body(
    const float* rel, const float* preBase, const unsigned char* Wp,
    const float* bx, const float* bh,
    float* relOut, float* R1, float* R2, int rb, int half)
{
    extern __shared__ char smc[];
    uint32_t sb = smem_u32(smc);
    int tid = threadIdx.x, wid = tid >> 5, lid = tid & 31;
    int wm = wid & 1, wn = wid >> 1;
    int row0 = rb * MTILE;

    float hv[2][4][4];
    #pragma unroll
    for (int mi = 0; mi < 2; mi++)
        #pragma unroll
        for (int rr = 0; rr < 2; rr++) {
            int row = wm*32 + mi*16 + rr*8 + (lid >> 2);
            int gr = row0 + row;
            bool rv = (gr < NR2);
            #pragma unroll
            for (int nj = 0; nj < 4; nj++) {
                int c = wn*32 + nj*8 + (lid & 3)*2;
                float o0 = 0.f, o1 = 0.f;
                if (rv) {
                    size_t ix = (size_t)gr*128 + c;
                    float2 hp  = *(const float2*)(rel + ix);
                    float2 xer = *(const float2*)(preBase + 0*(size_t)NR2*HDIM + ix);
                    float2 xez = *(const float2*)(preBase + 1*(size_t)NR2*HDIM + ix);
                    float2 xen = *(const float2*)(preBase + 2*(size_t)NR2*HDIM + ix);
                    float2 pxr = *(const float2*)(preBase + 3*(size_t)NR2*HDIM + ix);
                    float2 pxz = *(const float2*)(preBase + 4*(size_t)NR2*HDIM + ix);
                    float2 pxn = *(const float2*)(preBase + 5*(size_t)NR2*HDIM + ix);
                    float2 phr = *(const float2*)(preBase + 6*(size_t)NR2*HDIM + ix);
                    float2 phz = *(const float2*)(preBase + 7*(size_t)NR2*HDIM + ix);
                    float2 phn = *(const float2*)(preBase + 8*(size_t)NR2*HDIM + ix);
                    float r0 = sigf(xer.x + pxr.x + __ldg(bx+c)     + phr.x + __ldg(bh+c));
                    float r1 = sigf(xer.y + pxr.y + __ldg(bx+c+1)   + phr.y + __ldg(bh+c+1));
                    float z0 = sigf(xez.x + pxz.x + __ldg(bx+128+c) + phz.x + __ldg(bh+128+c));
                    float z1 = sigf(xez.y + pxz.y + __ldg(bx+129+c) + phz.y + __ldg(bh+129+c));
                    float n0 = tanhf(xen.x + pxn.x + __ldg(bx+256+c) + r0*(phn.x + __ldg(bh+256+c)));
                    float n1 = tanhf(xen.y + pxn.y + __ldg(bx+257+c) + r1*(phn.y + __ldg(bh+257+c)));
                    o0 = (1.f - z0)*n0 + z0*hp.x;
                    o1 = (1.f - z1)*n1 + z1*hp.y;
                    if (half == 0) *(float2*)(relOut + ix) = make_float2(o0, o1);
                }
                hv[mi][nj][rr*2] = o0; hv[mi][nj][rr*2+1] = o1;
            }
        }

    stage_W(sb, PG_W, Wp + (size_t)(half ? 2 : 0)*65536, tid);
    stage_A_r(smc, PG_A, hv, lid, wm, wn, (const float*)0, 0, 0);
    asm volatile("cp.async.wait_group 0;");
    __syncthreads();
    float acc[2][4][4]; ZERO_ACC(acc);
    gemm_tile(sb, PG_A, PG_W, lid, wm, wn, acc);
    write_plain(half ? R2 : R1, NR2, row0, lid, wm, wn, acc);
}

// standalone gru_combine (pre-loop only)
__global__ __launch_bounds__(NTHR, 2) void gru_combine(
    const float* __restrict__ rel, const float* __restrict__ preBase,
    const unsigned char* __restrict__ Wp,
    const float* __restrict__ bx, const float* __restrict__ bh,
    float* __restrict__ relOut, float* __restrict__ R1, float* __restrict__ R2) {
    gru_combine_body(rel, preBase, Wp, bx, bh, relOut, R1, R2,
                     blockIdx.x & 7, blockIdx.x >> 3);
}

// ---------------- K2: cur=leaky(HL+agg/deg) [elementwise]; HW=cur@Wn2; CL=cur@Wl2 ----------------
__global__ __launch_bounds__(NTHR, 2) void k2_kernel(
    const float* __restrict__ HL,
    const unsigned char* __restrict__ pWn2, const unsigned char* __restrict__ pWl2,
    float* __restrict__ HW, float* __restrict__ CL, int M,
    const float* __restrict__ agg, const float* __restrict__ deg,
    const float* __restrict__ relCur, const unsigned char* __restrict__ Wp,
    float* __restrict__ pre, int gridMain)
{
    if ((int)blockIdx.x >= gridMain) {
        gru_step_body(relCur, Wp, pre, blockIdx.x - gridMain);
        return;
    }
    extern __shared__ char smc[];
    uint32_t sb = smem_u32(smc);
    int tid = threadIdx.x, wid = tid >> 5, lid = tid & 31;
    int wm = wid & 1, wn = wid >> 1;
    int row0 = blockIdx.x * MTILE;

    stage_W(sb, PG_W, pWn2, tid);

    // cur fragments = leaky(agg/deg + HL), no GEMM
    float hv[2][4][4];
    #pragma unroll
    for (int mi = 0; mi < 2; mi++)
        #pragma unroll
        for (int rr = 0; rr < 2; rr++) {
            int gr = row0 + wm*32 + mi*16 + rr*8 + (lid >> 2);
            bool rv = (gr < M);
            float invdeg = rv ? 1.0f / fmaxf(__ldg(deg + gr), 1.0f) : 1.0f;
            #pragma unroll
            for (int nj = 0; nj < 4; nj++) {
                int c = wn*32 + nj*8 + (lid & 3)*2;
                float2 hl = rv ? *(const float2*)(HL + (size_t)gr*128 + c)
                               : make_float2(0.f, 0.f);
                float2 ag = rv ? *(const float2*)(agg + (size_t)gr*128 + c)
                               : make_float2(0.f, 0.f);
                float o0 = fmaf(ag.x, invdeg, hl.x);
                float o1 = fmaf(ag.y, invdeg, hl.y);
                o0 = o0 >= 0.f ? o0 : SLOPE*o0;
                o1 = o1 >= 0.f ? o1 : SLOPE*o1;
                hv[mi][nj][rr*2] = o0; hv[mi][nj][rr*2+1] = o1;
            }
        }

    stage_A_r(smc, PG_A, hv, lid, wm, wn, (const float*)0, 0, 0);
    asm volatile("cp.async.wait_group 0;");
    __syncthreads();

    float acc[2][4][4]; ZERO_ACC(acc);
    gemm_tile(sb, PG_A, PG_W, lid, wm, wn, acc);
    write_plain(HW, M, row0, lid, wm, wn, acc);
    __syncthreads();

    stage_W(sb, PG_W, pWl2, tid);
    asm volatile("cp.async.wait_group 0;");
    __syncthreads();
    ZERO_ACC(acc);
    gemm_tile(sb, PG_A, PG_W, lid, wm, wn, acc);
    write_plain(CL, M, row0, lid, wm, wn, acc);
}

// ---------------- K3: FINNORM(CL) + tail (+ next HW,HL) [+ fused gru_combine(t+1)] ----------------
__global__ __launch_bounds__(NTHR, 2) void k3_kernel(
    const float* __restrict__ CL, const float* __restrict__ h,
    const unsigned char* __restrict__ pTg,
    const unsigned char* __restrict__ pGa,  const unsigned char* __restrict__ pGb,
    const unsigned char* __restrict__ pTd,  const unsigned char* __restrict__ pWn1,
    const unsigned char* __restrict__ pWl1,
    const float* __restrict__ tgb, const float* __restrict__ gateb,
    const float* __restrict__ tdb,
    const float* __restrict__ agg, const float* __restrict__ deg,
    float* __restrict__ hout, float* __restrict__ HWout, float* __restrict__ HLout,
    int M, int doHW,
    const float* __restrict__ relCur, const float* __restrict__ pre,
    const unsigned char* __restrict__ Wp,
    const float* __restrict__ gbx, const float* __restrict__ gbh,
    float* __restrict__ relNext, float* __restrict__ R1, float* __restrict__ R2,
    int gridMain)
{
    if ((int)blockIdx.x >= gridMain) {
        int b = blockIdx.x - gridMain;
        gru_combine_body(relCur, pre, Wp, gbx, gbh, relNext, R1, R2, b & 7, b >> 3);
        return;
    }
    extern __shared__ char smc[];
    uint32_t sb = smem_u32(smc);
    int tid = threadIdx.x, wid = tid >> 5, lid = tid & 31;
    int wm = wid & 1, wn = wid >> 1;
    int row0 = blockIdx.x * MTILE;

    if (tid < 128) {
        ((float*)(smc + K3_BTG))[tid] = __ldg(tgb + tid);
        ((float*)(smc + K3_BGA))[tid] = __ldg(gateb + tid);
        ((float*)(smc + K3_BTD))[tid] = __ldg(tdb + tid);
    }
    const float* btg = (const float*)(smc + K3_BTG);
    const float* bga = (const float*)(smc + K3_BGA);
    const float* btd = (const float*)(smc + K3_BTD);
    float* sred = (float*)(smc + K3_SRED);

    float acc[2][4][4], hv[2][4][4];

    // ---- phase 0 (elementwise): nrm = l2norm(leaky(agg/deg + CL)) ----
    #pragma unroll
    for (int mi = 0; mi < 2; mi++)
        #pragma unroll
        for (int rr = 0; rr < 2; rr++) {
            int row = wm*32 + mi*16 + rr*8 + (lid >> 2);
            int gr = row0 + row;
            bool rv = (gr < M);
            float invdeg = rv ? 1.0f / fmaxf(__ldg(deg + gr), 1.0f) : 1.0f;
            float ss = 0.0f;
            #pragma unroll
            for (int nj = 0; nj < 4; nj++) {
                int c = wn*32 + nj*8 + (lid & 3)*2;
                float2 cl = rv ? *(const float2*)(CL + (size_t)gr*128 + c)
                               : make_float2(0.f, 0.f);
                float2 ag = rv ? *(const float2*)(agg + (size_t)gr*128 + c)
                               : make_float2(0.f, 0.f);
                float o0 = fmaf(ag.x, invdeg, cl.x);
                float o1 = fmaf(ag.y, invdeg, cl.y);
                o0 = o0 >= 0.f ? o0 : SLOPE*o0;
                o1 = o1 >= 0.f ? o1 : SLOPE*o1;
                hv[mi][nj][rr*2] = o0; hv[mi][nj][rr*2+1] = o1;
                ss += o0*o0 + o1*o1;
            }
            ss += __shfl_xor_sync(0xffffffffu, ss, 1);
            ss += __shfl_xor_sync(0xffffffffu, ss, 2);
            if ((lid & 3) == 0) sred[wn*64 + row] = ss;
        }
    __syncthreads();
    #pragma unroll
    for (int mi = 0; mi < 2; mi++)
        #pragma unroll
        for (int rr = 0; rr < 2; rr++) {
            int row = wm*32 + mi*16 + rr*8 + (lid >> 2);
            float tot = sred[row] + sred[64+row] + sred[128+row] + sred[192+row];
            float inv = 1.0f / fmaxf(sqrtf(tot), 1e-12f);
            #pragma unroll
            for (int nj = 0; nj < 4; nj++) { hv[mi][nj][rr*2] *= inv; hv[mi][nj][rr*2+1] *= inv; }
        }

    // ---- phase 1: time gate (nrm staged; h from gmem) ----
    stage_W(sb, K3_W, pTg, tid);
    stage_A_r(smc, K3_A1, hv, lid, wm, wn, (const float*)0, 0, 0);
    asm volatile("cp.async.wait_group 0;");
    __syncthreads();
    ZERO_ACC(acc);
    gemm_tile(sb, K3_A1, K3_W, lid, wm, wn, acc);
    #pragma unroll
    for (int mi = 0; mi < 2; mi++)
        #pragma unroll
        for (int rr = 0; rr < 2; rr++) {
            int row = wm*32 + mi*16 + rr*8 + (lid >> 2);
            int gr = row0 + row;
            bool rv = (gr < M);
            #pragma unroll
            for (int nj = 0; nj < 4; nj++) {
                int c = wn*32 + nj*8 + (lid & 3)*2;
                float2 nv = readA2(smc, K3_A1, row, c);
                float2 hh = rv ? *(const float2*)(h + (size_t)gr*128 + c)
                               : make_float2(0.f, 0.f);
                float g0 = sigf(acc[mi][nj][rr*2]   + btg[c]);
                float g1 = sigf(acc[mi][nj][rr*2+1] + btg[c+1]);
                hv[mi][nj][rr*2]   = g0*nv.x + (1.f-g0)*hh.x;
                hv[mi][nj][rr*2+1] = g1*nv.y + (1.f-g1)*hh.y;
            }
        }
    __syncthreads();

    // ---- phase 2: gated fusion (hn1@Ga + h@Gb) ----
    stage_W(sb, K3_W, pGa, tid);
    stage_A_r(smc, K3_A1, hv, lid, wm, wn, (const float*)0, 0, 0);
    asm volatile("cp.async.wait_group 0;");
    __syncthreads();
    ZERO_ACC(acc);
    gemm_tile(sb, K3_A1, K3_W, lid, wm, wn, acc);
    __syncthreads();
    stage_W(sb, K3_W, pGb, tid);
    stage_A_g(smc, K3_A1, h, row0, M, tid);     // A1 <- h
    asm volatile("cp.async.wait_group 0;");
    __syncthreads();
    gemm_tile(sb, K3_A1, K3_W, lid, wm, wn, acc);
    #pragma unroll
    for (int mi = 0; mi < 2; mi++)
        #pragma unroll
        for (int rr = 0; rr < 2; rr++) {
            int row = wm*32 + mi*16 + rr*8 + (lid >> 2);
            #pragma unroll
            for (int nj = 0; nj < 4; nj++) {
                int c = wn*32 + nj*8 + (lid & 3)*2;
                float2 hh = readA2(smc, K3_A1, row, c);   // h
                float g0 = sigf(acc[mi][nj][rr*2]   + bga[c]);
                float g1 = sigf(acc[mi][nj][rr*2+1] + bga[c+1]);
                hv[mi][nj][rr*2]   = g0*hv[mi][nj][rr*2]   + (1.f-g0)*hh.x;
                hv[mi][nj][rr*2+1] = g1*hv[mi][nj][rr*2+1] + (1.f-g1)*hh.y;
            }
        }
    __syncthreads();

    // ---- phase 3: tdiff  (stage hn2 - h; h read from gmem) ----
    stage_W(sb, K3_W, pTd, tid);
    stage_A_r(smc, K3_A1, hv, lid, wm, wn, h, row0, M);
    asm volatile("cp.async.wait_group 0;");
    __syncthreads();
    ZERO_ACC(acc);
    gemm_tile(sb, K3_A1, K3_W, lid, wm, wn, acc);
    #pragma unroll
    for (int mi = 0; mi < 2; mi++)
        #pragma unroll
        for (int rr = 0; rr < 2; rr++) {
            int gr = row0 + wm*32 + mi*16 + rr*8 + (lid >> 2);
            bool rv = (gr < M);
            #pragma unroll
            for (int nj = 0; nj < 4; nj++) {
                int c = wn*32 + nj*8 + (lid & 3)*2;
                float y0 = fmaxf(acc[mi][nj][rr*2]   + btd[c],   0.f);
                float y1 = fmaxf(acc[mi][nj][rr*2+1] + btd[c+1], 0.f);
                hv[mi][nj][rr*2]   += y0;
                hv[mi][nj][rr*2+1] += y1;
                if (rv) *(float2*)(hout + (size_t)gr*128 + c) =
                            make_float2(hv[mi][nj][rr*2], hv[mi][nj][rr*2+1]);
            }
        }

    // ---- phase 4 (optional): HW_next = h_next@Wn1; HL_next = h_next@Wl1 ----
    if (doHW) {
        __syncthreads();
        stage_W(sb, K3_W, pWn1, tid);
        stage_A_r(smc, K3_A1, hv, lid, wm, wn, (const float*)0, 0, 0);
        asm volatile("cp.async.wait_group 0;");
        __syncthreads();
        ZERO_ACC(acc);
        gemm_tile(sb, K3_A1, K3_W, lid, wm, wn, acc);
        write_plain(HWout, M, row0, lid, wm, wn, acc);
        __syncthreads();
        stage_W(sb, K3_W, pWl1, tid);
        asm volatile("cp.async.wait_group 0;");
        __syncthreads();
        ZERO_ACC(acc);
        gemm_tile(sb, K3_A1, K3_W, lid, wm, wn, acc);
        write_plain(HLout, M, row0, lid, wm, wn, acc);
    }
}

// ---------------- host driver ----------------
extern "C" void kernel_launch(void* const* d_in, const int* in_sizes, int n_in,
                              void* d_out, int out_size) {
    const int*   src     = (const int*)d_in[0];
    const int*   dst     = (const int*)d_in[1];
    const int*   ety     = (const int*)d_in[2];
    const float* dyn     = (const float*)d_in[3];
    const float* emb_rel = (const float*)d_in[4];
    const float* Wn1     = (const float*)d_in[5];
    const float* Wl1     = (const float*)d_in[6];
    const float* Wn2     = (const float*)d_in[7];
    const float* Wl2     = (const float*)d_in[8];
    const float* gWx     = (const float*)d_in[9];
    const float* gWh     = (const float*)d_in[10];
    const float* gbx     = (const float*)d_in[11];
    const float* gbh     = (const float*)d_in[12];
    const float* gateW   = (const float*)d_in[13];
    const float* gateb   = (const float*)d_in[14];
    const float* tdW     = (const float*)d_in[15];
    const float* tdb     = (const float*)d_in[16];
    const float* tgW     = (const float*)d_in[17];
    const float* tgb     = (const float*)d_in[18];
    float* out = (float*)d_out;

    float *hA,*hB,*CL,*HL,*HW,*agg,*relA,*relB,*R1,*R2,*pre;
    unsigned char* Wp;
    cudaGetSymbolAddress((void**)&hA,  g_hA);
    cudaGetSymbolAddress((void**)&hB,  g_hB);
    cudaGetSymbolAddress((void**)&CL,  g_CL);
    cudaGetSymbolAddress((void**)&HL,  g_HL);
    cudaGetSymbolAddress((void**)&HW,  g_HW);
    cudaGetSymbolAddress((void**)&agg, g_agg);
    cudaGetSymbolAddress((void**)&relA,g_relA);
    cudaGetSymbolAddress((void**)&relB,g_relB);
    cudaGetSymbolAddress((void**)&R1,  g_R1);
    cudaGetSymbolAddress((void**)&R2,  g_R2);
    cudaGetSymbolAddress((void**)&pre, g_pre);
    cudaGetSymbolAddress((void**)&Wp,  g_Wpack);
    float* deg = agg + (size_t)NENT*HDIM;

    cudaFuncSetAttribute((const void*)plain_gemm,  cudaFuncAttributeMaxDynamicSharedMemorySize, PG_SIZE);
    cudaFuncSetAttribute((const void*)gru_pre,     cudaFuncAttributeMaxDynamicSharedMemorySize, PG_SIZE);
    cudaFuncSetAttribute((const void*)gru_step,    cudaFuncAttributeMaxDynamicSharedMemorySize, PG_SIZE);
    cudaFuncSetAttribute((const void*)gru_combine, cudaFuncAttributeMaxDynamicSharedMemorySize, PG_SIZE);
    cudaFuncSetAttribute((const void*)k2_kernel,   cudaFuncAttributeMaxDynamicSharedMemorySize, PG_SIZE);
    cudaFuncSetAttribute((const void*)k3_kernel,   cudaFuncAttributeMaxDynamicSharedMemorySize, K3_SIZE);

    const unsigned char* pWn1 = Wp + 0*65536;
    const unsigned char* pWl1 = Wp + 1*65536;
    const unsigned char* pWn2 = Wp + 2*65536;
    const unsigned char* pWl2 = Wp + 3*65536;
    const unsigned char* pTg  = Wp + 4*65536;
    const unsigned char* pGa  = Wp + 5*65536;
    const unsigned char* pGb  = Wp + 6*65536;
    const unsigned char* pTd  = Wp + 7*65536;

    const int GB = (NENT + MTILE - 1) / MTILE;   // 1563
    const int EB = (EE*32 + 255) / 256;

    pack_kernel<<<17, 256>>>(Wn1, Wl1, Wn2, Wl2, tgW, gateW, tdW, gWx, gWh);
    l2norm_kernel<<<(NENT + 7)/8, 256>>>(dyn, hA, NENT);
    gru_pre<<<24, NTHR, PG_SIZE>>>(emb_rel, Wp, pre);
    plain_gemm<<<GB, NTHR, PG_SIZE>>>(hA, pWn1, HW, NENT);
    plain_gemm<<<GB, NTHR, PG_SIZE>>>(hA, pWl1, HL, NENT);
    // step-0 GRU: rel(0), R1(0), R2(0)
    gru_step<<<48, NTHR, PG_SIZE>>>(emb_rel, Wp, pre);
    gru_combine<<<16, NTHR, PG_SIZE>>>(emb_rel, pre, Wp, gbx, gbh, relA, R1, R2);

    float* relBufs[2] = { relA, relB };
    float* h     = hA;
    float* hnext = hB;

    for (int t = 0; t < TT; t++) {
        const int* sT = src + t*EE;
        const int* dT = dst + t*EE;
        const int* eT = ety + t*EE;
        float* relCur  = relBufs[t & 1];        // rel(t)
        float* relNext = relBufs[(t + 1) & 1];  // rel(t+1)

        // single memset (agg+deg contiguous) immediately before edge1: L2-hot for atomics
        cudaMemsetAsync(agg, 0, ((size_t)NENT*HDIM + NENT)*sizeof(float));

        // layer 1; k2 tail blocks run gru_step(t+1) on rel(t)
        edge_kernel<<<EB, 256>>>(sT, dT, eT, HW, R1, agg, deg, EE, 1);
        k2_kernel<<<GB + 48, NTHR, PG_SIZE>>>(HL, pWn2, pWl2, HW, CL, NENT, agg, deg,
                                              relCur, Wp, pre, GB);

        // layer 2
        cudaMemsetAsync(agg, 0, (size_t)NENT*HDIM*sizeof(float));
        edge_kernel<<<EB, 256>>>(sT, dT, eT, HW, R2, agg, deg, EE, 0);

        // k3 tail blocks run gru_combine(t+1): rel(t+1), R1(t+1), R2(t+1)
        float* target = (t == TT-1) ? out : hnext;
        k3_kernel<<<GB + 16, NTHR, K3_SIZE>>>(CL, h, pTg, pGa, pGb, pTd, pWn1, pWl1,
                                              tgb, gateb, tdb, agg, deg,
                                              target, HW, HL, NENT, (t < TT-1) ? 1 : 0,
                                              relCur, pre, Wp, gbx, gbh,
                                              relNext, R1, R2, GB);

        if (t < TT-1) { float* tmp = h; h = hnext; hnext = tmp; }
    }
}

// round 17
// speedup vs baseline: 1.0671x; 1.0671x over previous
#include <cuda_runtime.h>
#include <cuda_bf16.h>
#include <cstdint>
#include <math.h>

// ---------------- problem constants ----------------
#define NENT   100000
#define HDIM   128
#define NR2    460
#define TT     4
#define EE     200000
#define SLOPE  0.22916666666666666f
#define NTHR   256
#define MTILE  64

// ---- smem layouts (A: 16KB hi + 16KB lo; W: 32KB hi + 32KB lo) ----
#define PG_A     0
#define PG_W     32768
#define PG_SIZE  98304
#define K3_BTG   0
#define K3_BGA   512
#define K3_BTD   1024
#define K3_SRED  1536
#define K3_A1    4096
#define K3_W     (K3_A1 + 32768)
#define K3_SIZE  (K3_W + 65536)      // 102400 -> 2 CTAs/SM

// ---------------- scratch ----------------
__device__ float g_hA [NENT*HDIM];
__device__ float g_hB [NENT*HDIM];
__device__ float g_cur[NENT*HDIM];
__device__ float g_HW [NENT*HDIM];
__device__ float g_agg[NENT*HDIM + NENT];   // deg appended -> single memset
__device__ float g_relA[NR2*HDIM];
__device__ float g_relB[NR2*HDIM];
__device__ float g_R1 [NR2*HDIM];
__device__ float g_R2 [NR2*HDIM];
__device__ float g_pre[9][NR2*HDIM];
__device__ unsigned char g_Wpack[17][65536];

__device__ __forceinline__ float sigf(float x) { return 1.0f / (1.0f + __expf(-x)); }

__device__ __forceinline__ uint32_t smem_u32(const void* p) {
    uint32_t a;
    asm("{ .reg .u64 t; cvta.to.shared.u64 t, %1; cvt.u32.u64 %0, t; }" : "=r"(a) : "l"(p));
    return a;
}
__device__ __host__ __forceinline__ uint32_t swz(uint32_t off) {
    return off ^ ((off >> 4) & 0x70);
}
__device__ __forceinline__ void ldsm4(uint32_t* r, uint32_t a) {
    asm volatile("ldmatrix.sync.aligned.m8n8.x4.shared.b16 {%0,%1,%2,%3}, [%4];"
                 : "=r"(r[0]),"=r"(r[1]),"=r"(r[2]),"=r"(r[3]) : "r"(a));
}
__device__ __forceinline__ void ldsm4t(uint32_t* r, uint32_t a) {
    asm volatile("ldmatrix.sync.aligned.m8n8.x4.trans.shared.b16 {%0,%1,%2,%3}, [%4];"
                 : "=r"(r[0]),"=r"(r[1]),"=r"(r[2]),"=r"(r[3]) : "r"(a));
}
__device__ __forceinline__ void mma16816(float* d, const uint32_t* a, uint32_t b0, uint32_t b1) {
    asm volatile("mma.sync.aligned.m16n8k16.row.col.f32.bf16.bf16.f32 "
                 "{%0,%1,%2,%3},{%4,%5,%6,%7},{%8,%9},{%0,%1,%2,%3};"
                 : "+f"(d[0]),"+f"(d[1]),"+f"(d[2]),"+f"(d[3])
                 : "r"(a[0]),"r"(a[1]),"r"(a[2]),"r"(a[3]),"r"(b0),"r"(b1));
}
__device__ __forceinline__ void cp16(uint32_t saddr, const void* gaddr) {
    asm volatile("cp.async.cg.shared.global [%0], [%1], 16;" :: "r"(saddr), "l"(gaddr));
}

// ---------------- weight pack ----------------
__global__ void pack_kernel(const float* __restrict__ Wn1, const float* __restrict__ Wl1,
                            const float* __restrict__ Wn2, const float* __restrict__ Wl2,
                            const float* __restrict__ tgW, const float* __restrict__ gateW,
                            const float* __restrict__ tdW,
                            const float* __restrict__ gWx, const float* __restrict__ gWh) {
    int m = blockIdx.x;
    unsigned char* base = g_Wpack[m];
    for (int idx = threadIdx.x; idx < 16384; idx += blockDim.x) {
        int k = idx >> 7, n = idx & 127;
        float v;
        if      (m == 0) v = Wn1[k * 128 + n];
        else if (m == 1) v = Wl1[k * 128 + n];
        else if (m == 2) v = Wn2[k * 128 + n];
        else if (m == 3) v = Wl2[k * 128 + n];
        else if (m == 4) v = tgW[k * 128 + n];
        else if (m == 5) v = gateW[n * 256 + k];
        else if (m == 6) v = gateW[n * 256 + 128 + k];
        else if (m == 7) v = tdW[n * 128 + k];
        else if (m < 14) {
            int g = (m - 8) >> 1, kt = (m - 8) & 1;
            v = gWx[(g * 128 + n) * 256 + kt * 128 + k];
        } else {
            int g = m - 14;
            v = gWh[(g * 128 + n) * 128 + k];
        }
        __nv_bfloat16 hi = __float2bfloat16(v);
        __nv_bfloat16 lo = __float2bfloat16(v - __bfloat162float(hi));
        uint32_t o = swz((uint32_t)(k * 256 + n * 2));
        *(__nv_bfloat16*)(base + o)         = hi;
        *(__nv_bfloat16*)(base + 32768 + o) = lo;
    }
}

// ---------------- l2norm ----------------
__global__ void l2norm_kernel(const float* __restrict__ in, float* __restrict__ out, int M) {
    int w = (blockIdx.x * blockDim.x + threadIdx.x) >> 5;
    int lane = threadIdx.x & 31;
    if (w >= M) return;
    float4 v = ((const float4*)in)[w*32 + lane];
    float ss = v.x*v.x + v.y*v.y + v.z*v.z + v.w*v.w;
    #pragma unroll
    for (int o = 16; o; o >>= 1) ss += __shfl_xor_sync(0xffffffffu, ss, o);
    float inv = 1.0f / fmaxf(sqrtf(ss), 1e-12f);
    v.x *= inv; v.y *= inv; v.z *= inv; v.w *= inv;
    ((float4*)out)[w*32 + lane] = v;
}

// ---------------- edge gather + vector-atomic scatter (2 edges/warp, MLP=2) ----------------
__global__ void edge_kernel(const int* __restrict__ src, const int* __restrict__ dst,
                            const int* __restrict__ ety, const float* __restrict__ HW,
                            const float* __restrict__ R, float* __restrict__ agg,
                            float* __restrict__ deg, int E, int do_deg) {
    int w = (blockIdx.x * blockDim.x + threadIdx.x) >> 5;
    int lane = threadIdx.x & 31;
    int e0 = w * 2, e1 = e0 + 1;
    if (e0 >= E) return;
    bool has1 = (e1 < E);
    int s0 = __ldg(src + e0), d0 = __ldg(dst + e0), r0 = __ldg(ety + e0);
    int s1 = has1 ? __ldg(src + e1) : s0;
    int d1 = has1 ? __ldg(dst + e1) : d0;
    int r1 = has1 ? __ldg(ety + e1) : r0;
    // issue both gathers before consuming either (MLP=2)
    float4 v0  = __ldg(((const float4*)HW) + (size_t)s0*32 + lane);
    float4 v1  = __ldg(((const float4*)HW) + (size_t)s1*32 + lane);
    float4 rv0 = __ldg(((const float4*)R)  + (size_t)r0*32 + lane);
    float4 rv1 = __ldg(((const float4*)R)  + (size_t)r1*32 + lane);
    v0.x += rv0.x; v0.y += rv0.y; v0.z += rv0.z; v0.w += rv0.w;
    float* p0 = agg + (size_t)d0*128 + lane*4;
    asm volatile("red.global.add.v4.f32 [%0], {%1,%2,%3,%4};"
                 :: "l"(p0), "f"(v0.x), "f"(v0.y), "f"(v0.z), "f"(v0.w) : "memory");
    if (do_deg && lane == 0) atomicAdd(deg + d0, 1.0f);
    if (has1) {
        v1.x += rv1.x; v1.y += rv1.y; v1.z += rv1.z; v1.w += rv1.w;
        float* p1 = agg + (size_t)d1*128 + lane*4;
        asm volatile("red.global.add.v4.f32 [%0], {%1,%2,%3,%4};"
                     :: "l"(p1), "f"(v1.x), "f"(v1.y), "f"(v1.z), "f"(v1.w) : "memory");
        if (do_deg && lane == 0) atomicAdd(deg + d1, 1.0f);
    }
}

// ---------------- staging (64-row tiles) ----------------
__device__ __forceinline__ void stage_A_g(char* smc, int dstOff, const float* A,
                                          int row0, int M, int tid) {
    #pragma unroll
    for (int it = 0; it < 4; it++) {
        int i = tid + it * NTHR;
        int r = i >> 4, c8 = i & 15;
        int gr = row0 + r;
        float4 v0 = make_float4(0.f,0.f,0.f,0.f), v1 = v0;
        if (gr < M) {
            v0 = __ldg(((const float4*)A) + (size_t)gr*32 + c8*2);
            v1 = __ldg(((const float4*)A) + (size_t)gr*32 + c8*2 + 1);
        }
        float f[8] = {v0.x, v0.y, v0.z, v0.w, v1.x, v1.y, v1.z, v1.w};
        __nv_bfloat162 hi[4], lo[4];
        #pragma unroll
        for (int q = 0; q < 4; q++) {
            __nv_bfloat16 hx = __float2bfloat16(f[2*q]);
            __nv_bfloat16 hy = __float2bfloat16(f[2*q+1]);
            hi[q].x = hx; hi[q].y = hy;
            lo[q].x = __float2bfloat16(f[2*q]   - __bfloat162float(hx));
            lo[q].y = __float2bfloat16(f[2*q+1] - __bfloat162float(hy));
        }
        uint32_t off = swz((uint32_t)(r*256 + c8*16));
        *(uint4*)(smc + dstOff + off)         = *(uint4*)hi;
        *(uint4*)(smc + dstOff + 16384 + off) = *(uint4*)lo;
    }
}
__device__ __forceinline__ void stage_W(uint32_t sb, int dstOff, const unsigned char* Wimg, int tid) {
    uint32_t s = sb + dstOff;
    #pragma unroll 2
    for (int i = tid; i < 4096; i += NTHR) cp16(s + i*16, Wimg + (size_t)i*16);
    asm volatile("cp.async.commit_group;");
}
__device__ __forceinline__ float2 readA2(const char* smc, int off, int row, int c) {
    uint32_t o = swz((uint32_t)(row*256 + c*2));
    __nv_bfloat162 h = *(const __nv_bfloat162*)(smc + off + o);
    __nv_bfloat162 l = *(const __nv_bfloat162*)(smc + off + 16384 + o);
    return make_float2(__bfloat162float(h.x) + __bfloat162float(l.x),
                       __bfloat162float(h.y) + __bfloat162float(l.y));
}
// fragments -> smem hi/lo; gsub: subtract gmem fp32 rows
__device__ __forceinline__ void stage_A_r(char* smc, int dstOff, const float hv[2][4][4],
                                          int lid, int wm, int wn,
                                          const float* gsub, int row0, int M) {
    #pragma unroll
    for (int mi = 0; mi < 2; mi++)
        #pragma unroll
        for (int rr = 0; rr < 2; rr++) {
            int row = wm*32 + mi*16 + rr*8 + (lid >> 2);
            int gr = row0 + row;
            bool rv = gsub && (gr < M);
            #pragma unroll
            for (int nj = 0; nj < 4; nj++) {
                int c = wn*32 + nj*8 + (lid & 3)*2;
                float v0 = hv[mi][nj][rr*2], v1 = hv[mi][nj][rr*2+1];
                if (gsub) {
                    float2 s = rv ? *(const float2*)(gsub + (size_t)gr*128 + c)
                                  : make_float2(0.f, 0.f);
                    v0 -= s.x; v1 -= s.y;
                }
                __nv_bfloat16 h0 = __float2bfloat16(v0), h1 = __float2bfloat16(v1);
                __nv_bfloat162 hi2, lo2;
                hi2.x = h0; hi2.y = h1;
                lo2.x = __float2bfloat16(v0 - __bfloat162float(h0));
                lo2.y = __float2bfloat16(v1 - __bfloat162float(h1));
                uint32_t o = swz((uint32_t)(row*256 + c*2));
                *(__nv_bfloat162*)(smc + dstOff + o)         = hi2;
                *(__nv_bfloat162*)(smc + dstOff + 16384 + o) = lo2;
            }
        }
}

// ---------------- mainloop: warp tile 32x32, split-bf16 ----------------
__device__ __forceinline__ void gemm_tile(uint32_t sb, uint32_t aOff, uint32_t wOff,
                                          int lid, int wm, int wn, float acc[2][4][4]) {
    #pragma unroll
    for (int k0 = 0; k0 < 128; k0 += 16) {
        uint32_t aH[2][4], aL[2][4];
        #pragma unroll
        for (int mi = 0; mi < 2; mi++) {
            int row = wm*32 + mi*16 + (lid & 15);
            int col = k0 + ((lid >> 4) << 3);
            uint32_t off = swz((uint32_t)(row*256 + col*2));
            ldsm4(aH[mi], sb + aOff + off);
            ldsm4(aL[mi], sb + aOff + 16384 + off);
        }
        uint32_t bH[2][4], bL[2][4];
        #pragma unroll
        for (int pi = 0; pi < 2; pi++) {
            int krow = k0 + (lid & 15);
            int col  = wn*32 + pi*16 + ((lid >> 4) << 3);
            uint32_t off = swz((uint32_t)(krow*256 + col*2));
            ldsm4t(bH[pi], sb + wOff + off);
            ldsm4t(bL[pi], sb + wOff + 32768 + off);
        }
        #pragma unroll
        for (int mi = 0; mi < 2; mi++)
            #pragma unroll
            for (int nj = 0; nj < 4; nj++) {
                int pi = nj >> 1, o = (nj & 1) * 2;
                mma16816(acc[mi][nj], aH[mi], bH[pi][o], bH[pi][o+1]);
                mma16816(acc[mi][nj], aL[mi], bH[pi][o], bH[pi][o+1]);
                mma16816(acc[mi][nj], aH[mi], bL[pi][o], bL[pi][o+1]);
            }
    }
}
#define ZERO_ACC(acc) { _Pragma("unroll") for (int a_=0;a_<2;a_++) _Pragma("unroll") for (int b_=0;b_<4;b_++) _Pragma("unroll") for (int c_=0;c_<4;c_++) acc[a_][b_][c_]=0.0f; }

__device__ __forceinline__ void write_plain(float* C, int M, int row0, int lid, int wm, int wn,
                                            const float acc[2][4][4]) {
    #pragma unroll
    for (int mi = 0; mi < 2; mi++)
        #pragma unroll
        for (int rr = 0; rr < 2; rr++) {
            int gr = row0 + wm*32 + mi*16 + rr*8 + (lid >> 2);
            if (gr >= M) continue;
            #pragma unroll
            for (int nj = 0; nj < 4; nj++) {
                int c = wn*32 + nj*8 + (lid & 3)*2;
                *(float2*)(C + (size_t)gr*128 + c) =
                    make_float2(acc[mi][nj][rr*2], acc[mi][nj][rr*2+1]);
            }
        }
}

// ---------------- plain GEMM body ----------------
__device__ __forceinline__ void plain_body(const float* A, const unsigned char* Wimg,
                                           float* C, int M, int row0) {
    extern __shared__ char smc[];
    uint32_t sb = smem_u32(smc);
    int tid = threadIdx.x, wid = tid >> 5, lid = tid & 31;
    int wm = wid & 1, wn = wid >> 1;
    stage_W(sb, PG_W, Wimg, tid);
    stage_A_g(smc, PG_A, A, row0, M, tid);
    asm volatile("cp.async.wait_group 0;");
    __syncthreads();
    float acc[2][4][4]; ZERO_ACC(acc);
    gemm_tile(sb, PG_A, PG_W, lid, wm, wn, acc);
    write_plain(C, M, row0, lid, wm, wn, acc);
}

__global__ __launch_bounds__(NTHR, 2) void plain_gemm(
    const float* __restrict__ A, const unsigned char* __restrict__ Wimg,
    float* __restrict__ C, int M) {
    plain_body(A, Wimg, C, M, blockIdx.x * MTILE);
}

// gru_step body: pre[3+prod] = rel @ W(prod)
__device__ __forceinline__ void gru_step_body(const float* rel, const unsigned char* Wp,
                                              float* preBase, int b) {
    int prod = b >> 3, rb = b & 7;
    const unsigned char* W = Wp + (size_t)((prod < 3) ? (8 + 2*prod + 1) : (14 + prod - 3))*65536;
    plain_body(rel, W, preBase + (size_t)(3 + prod)*NR2*HDIM, NR2, rb * MTILE);
}

// XE precompute (once)
__global__ __launch_bounds__(NTHR, 2) void gru_pre(
    const float* __restrict__ emb_rel, const unsigned char* __restrict__ Wp,
    float* __restrict__ preBase) {
    int g = blockIdx.x >> 3, rb = blockIdx.x & 7;
    plain_body(emb_rel, Wp + (size_t)(8 + 2*g)*65536,
               preBase + (size_t)g*NR2*HDIM, NR2, rb * MTILE);
}
// standalone gru_step (pre-loop only)
__global__ __launch_bounds__(NTHR, 2) void gru_step(
    const float* __restrict__ rel, const unsigned char* __restrict__ Wp,
    float* __restrict__ preBase) {
    gru_step_body(rel, Wp, preBase, blockIdx.x);
}

// ---------------- gru_combine body ----------------
__device__ __forceinline__ void gru_combine_body(
    const float* rel, const float* preBase, const unsigned char* Wp,
    const float* bx, const float* bh,
    float* relOut, float* R1, float* R2, int rb, int half)
{
    extern __shared__ char smc[];
    uint32_t sb = smem_u32(smc);
    int tid = threadIdx.x, wid = tid >> 5, lid = tid & 31;
    int wm = wid & 1, wn = wid >> 1;
    int row0 = rb * MTILE;

    float hv[2][4][4];
    #pragma unroll
    for (int mi = 0; mi < 2; mi++)
        #pragma unroll
        for (int rr = 0; rr < 2; rr++) {
            int row = wm*32 + mi*16 + rr*8 + (lid >> 2);
            int gr = row0 + row;
            bool rv = (gr < NR2);
            #pragma unroll
            for (int nj = 0; nj < 4; nj++) {
                int c = wn*32 + nj*8 + (lid & 3)*2;
                float o0 = 0.f, o1 = 0.f;
                if (rv) {
                    size_t ix = (size_t)gr*128 + c;
                    float2 hp  = *(const float2*)(rel + ix);
                    float2 xer = *(const float2*)(preBase + 0*(size_t)NR2*HDIM + ix);
                    float2 xez = *(const float2*)(preBase + 1*(size_t)NR2*HDIM + ix);
                    float2 xen = *(const float2*)(preBase + 2*(size_t)NR2*HDIM + ix);
                    float2 pxr = *(const float2*)(preBase + 3*(size_t)NR2*HDIM + ix);
                    float2 pxz = *(const float2*)(preBase + 4*(size_t)NR2*HDIM + ix);
                    float2 pxn = *(const float2*)(preBase + 5*(size_t)NR2*HDIM + ix);
                    float2 phr = *(const float2*)(preBase + 6*(size_t)NR2*HDIM + ix);
                    float2 phz = *(const float2*)(preBase + 7*(size_t)NR2*HDIM + ix);
                    float2 phn = *(const float2*)(preBase + 8*(size_t)NR2*HDIM + ix);
                    float r0 = sigf(xer.x + pxr.x + __ldg(bx+c)     + phr.x + __ldg(bh+c));
                    float r1 = sigf(xer.y + pxr.y + __ldg(bx+c+1)   + phr.y + __ldg(bh+c+1));
                    float z0 = sigf(xez.x + pxz.x + __ldg(bx+128+c) + phz.x + __ldg(bh+128+c));
                    float z1 = sigf(xez.y + pxz.y + __ldg(bx+129+c) + phz.y + __ldg(bh+129+c));
                    float n0 = tanhf(xen.x + pxn.x + __ldg(bx+256+c) + r0*(phn.x + __ldg(bh+256+c)));
                    float n1 = tanhf(xen.y + pxn.y + __ldg(bx+257+c) + r1*(phn.y + __ldg(bh+257+c)));
                    o0 = (1.f - z0)*n0 + z0*hp.x;
                    o1 = (1.f - z1)*n1 + z1*hp.y;
                    if (half == 0) *(float2*)(relOut + ix) = make_float2(o0, o1);
                }
                hv[mi][nj][rr*2] = o0; hv[mi][nj][rr*2+1] = o1;
            }
        }

    stage_W(sb, PG_W, Wp + (size_t)(half ? 2 : 0)*65536, tid);
    stage_A_r(smc, PG_A, hv, lid, wm, wn, (const float*)0, 0, 0);
    asm volatile("cp.async.wait_group 0;");
    __syncthreads();
    float acc[2][4][4]; ZERO_ACC(acc);
    gemm_tile(sb, PG_A, PG_W, lid, wm, wn, acc);
    write_plain(half ? R2 : R1, NR2, row0, lid, wm, wn, acc);
}

// standalone gru_combine (pre-loop only)
__global__ __launch_bounds__(NTHR, 2) void gru_combine(
    const float* __restrict__ rel, const float* __restrict__ preBase,
    const unsigned char* __restrict__ Wp,
    const float* __restrict__ bx, const float* __restrict__ bh,
    float* __restrict__ relOut, float* __restrict__ R1, float* __restrict__ R2) {
    gru_combine_body(rel, preBase, Wp, bx, bh, relOut, R1, R2,
                     blockIdx.x & 7, blockIdx.x >> 3);
}

// ---------------- K2: cur = FIN(h@Wl1, agg); HW = cur@Wn2 [+ fused gru_step(t+1)] ----------------
__global__ __launch_bounds__(NTHR, 2) void k2_kernel(
    const float* __restrict__ h,
    const unsigned char* __restrict__ pWl1, const unsigned char* __restrict__ pWn2,
    float* __restrict__ cur, float* __restrict__ HW, int M,
    const float* __restrict__ agg, const float* __restrict__ deg,
    const float* __restrict__ relCur, const unsigned char* __restrict__ Wp,
    float* __restrict__ pre, int gridMain)
{
    if ((int)blockIdx.x >= gridMain) {
        gru_step_body(relCur, Wp, pre, blockIdx.x - gridMain);
        return;
    }
    extern __shared__ char smc[];
    uint32_t sb = smem_u32(smc);
    int tid = threadIdx.x, wid = tid >> 5, lid = tid & 31;
    int wm = wid & 1, wn = wid >> 1;
    int row0 = blockIdx.x * MTILE;

    stage_W(sb, PG_W, pWl1, tid);
    stage_A_g(smc, PG_A, h, row0, M, tid);
    asm volatile("cp.async.wait_group 0;");
    __syncthreads();

    float acc[2][4][4]; ZERO_ACC(acc);
    gemm_tile(sb, PG_A, PG_W, lid, wm, wn, acc);

    float hv[2][4][4];
    #pragma unroll
    for (int mi = 0; mi < 2; mi++)
        #pragma unroll
        for (int rr = 0; rr < 2; rr++) {
            int gr = row0 + wm*32 + mi*16 + rr*8 + (lid >> 2);
            bool rv = (gr < M);
            float invdeg = rv ? 1.0f / fmaxf(__ldg(deg + gr), 1.0f) : 1.0f;
            #pragma unroll
            for (int nj = 0; nj < 4; nj++) {
                int c = wn*32 + nj*8 + (lid & 3)*2;
                float2 ag = rv ? *(const float2*)(agg + (size_t)gr*128 + c)
                               : make_float2(0.f, 0.f);
                float o0 = fmaf(ag.x, invdeg, acc[mi][nj][rr*2]);
                float o1 = fmaf(ag.y, invdeg, acc[mi][nj][rr*2+1]);
                o0 = o0 >= 0.f ? o0 : SLOPE*o0;
                o1 = o1 >= 0.f ? o1 : SLOPE*o1;
                hv[mi][nj][rr*2] = o0; hv[mi][nj][rr*2+1] = o1;
                if (rv) *(float2*)(cur + (size_t)gr*128 + c) = make_float2(o0, o1);
            }
        }
    __syncthreads();

    stage_W(sb, PG_W, pWn2, tid);
    stage_A_r(smc, PG_A, hv, lid, wm, wn, (const float*)0, 0, 0);
    asm volatile("cp.async.wait_group 0;");
    __syncthreads();
    ZERO_ACC(acc);
    gemm_tile(sb, PG_A, PG_W, lid, wm, wn, acc);
    write_plain(HW, M, row0, lid, wm, wn, acc);
}

// ---------------- K3: FINNORM + tail (+ next h@Wn1) [+ fused gru_combine(t+1)] ----------------
__global__ __launch_bounds__(NTHR, 2) void k3_kernel(
    const float* __restrict__ cur, const float* __restrict__ h,
    const unsigned char* __restrict__ pWl2, const unsigned char* __restrict__ pTg,
    const unsigned char* __restrict__ pGa,  const unsigned char* __restrict__ pGb,
    const unsigned char* __restrict__ pTd,  const unsigned char* __restrict__ pWn1,
    const float* __restrict__ tgb, const float* __restrict__ gateb,
    const float* __restrict__ tdb,
    const float* __restrict__ agg, const float* __restrict__ deg,
    float* __restrict__ hout, float* __restrict__ HWout, int M, int doHW,
    const float* __restrict__ relCur, const float* __restrict__ pre,
    const unsigned char* __restrict__ Wp,
    const float* __restrict__ gbx, const float* __restrict__ gbh,
    float* __restrict__ relNext, float* __restrict__ R1, float* __restrict__ R2,
    int gridMain)
{
    if ((int)blockIdx.x >= gridMain) {
        int b = blockIdx.x - gridMain;
        gru_combine_body(relCur, pre, Wp, gbx, gbh, relNext, R1, R2, b & 7, b >> 3);
        return;
    }
    extern __shared__ char smc[];
    uint32_t sb = smem_u32(smc);
    int tid = threadIdx.x, wid = tid >> 5, lid = tid & 31;
    int wm = wid & 1, wn = wid >> 1;
    int row0 = blockIdx.x * MTILE;

    if (tid < 128) {
        ((float*)(smc + K3_BTG))[tid] = __ldg(tgb + tid);
        ((float*)(smc + K3_BGA))[tid] = __ldg(gateb + tid);
        ((float*)(smc + K3_BTD))[tid] = __ldg(tdb + tid);
    }
    stage_W(sb, K3_W, pWl2, tid);
    stage_A_g(smc, K3_A1, cur, row0, M, tid);
    asm volatile("cp.async.wait_group 0;");
    __syncthreads();

    const float* btg = (const float*)(smc + K3_BTG);
    const float* bga = (const float*)(smc + K3_BGA);
    const float* btd = (const float*)(smc + K3_BTD);
    float* sred = (float*)(smc + K3_SRED);

    float acc[2][4][4], hv[2][4][4];

    // ---- phase 0: nrm = l2norm(leaky(agg/deg + cur@Wl2)) ----
    ZERO_ACC(acc);
    gemm_tile(sb, K3_A1, K3_W, lid, wm, wn, acc);
    #pragma unroll
    for (int mi = 0; mi < 2; mi++)
        #pragma unroll
        for (int rr = 0; rr < 2; rr++) {
            int row = wm*32 + mi*16 + rr*8 + (lid >> 2);
            int gr = row0 + row;
            bool rv = (gr < M);
            float invdeg = rv ? 1.0f / fmaxf(__ldg(deg + gr), 1.0f) : 1.0f;
            float ss = 0.0f;
            #pragma unroll
            for (int nj = 0; nj < 4; nj++) {
                int c = wn*32 + nj*8 + (lid & 3)*2;
                float2 ag = rv ? *(const float2*)(agg + (size_t)gr*128 + c)
                               : make_float2(0.f, 0.f);
                float o0 = fmaf(ag.x, invdeg, acc[mi][nj][rr*2]);
                float o1 = fmaf(ag.y, invdeg, acc[mi][nj][rr*2+1]);
                o0 = o0 >= 0.f ? o0 : SLOPE*o0;
                o1 = o1 >= 0.f ? o1 : SLOPE*o1;
                hv[mi][nj][rr*2] = o0; hv[mi][nj][rr*2+1] = o1;
                ss += o0*o0 + o1*o1;
            }
            ss += __shfl_xor_sync(0xffffffffu, ss, 1);
            ss += __shfl_xor_sync(0xffffffffu, ss, 2);
            if ((lid & 3) == 0) sred[wn*64 + row] = ss;
        }
    __syncthreads();
    #pragma unroll
    for (int mi = 0; mi < 2; mi++)
        #pragma unroll
        for (int rr = 0; rr < 2; rr++) {
            int row = wm*32 + mi*16 + rr*8 + (lid >> 2);
            float tot = sred[row] + sred[64+row] + sred[128+row] + sred[192+row];
            float inv = 1.0f / fmaxf(sqrtf(tot), 1e-12f);
            #pragma unroll
            for (int nj = 0; nj < 4; nj++) { hv[mi][nj][rr*2] *= inv; hv[mi][nj][rr*2+1] *= inv; }
        }
    __syncthreads();

    // ---- phase 1: time gate (nrm staged; h from gmem) ----
    stage_W(sb, K3_W, pTg, tid);
    stage_A_r(smc, K3_A1, hv, lid, wm, wn, (const float*)0, 0, 0);
    asm volatile("cp.async.wait_group 0;");
    __syncthreads();
    ZERO_ACC(acc);
    gemm_tile(sb, K3_A1, K3_W, lid, wm, wn, acc);
    #pragma unroll
    for (int mi = 0; mi < 2; mi++)
        #pragma unroll
        for (int rr = 0; rr < 2; rr++) {
            int row = wm*32 + mi*16 + rr*8 + (lid >> 2);
            int gr = row0 + row;
            bool rv = (gr < M);
            #pragma unroll
            for (int nj = 0; nj < 4; nj++) {
                int c = wn*32 + nj*8 + (lid & 3)*2;
                float2 nv = readA2(smc, K3_A1, row, c);
                float2 hh = rv ? *(const float2*)(h + (size_t)gr*128 + c)
                               : make_float2(0.f, 0.f);
                float g0 = sigf(acc[mi][nj][rr*2]   + btg[c]);
                float g1 = sigf(acc[mi][nj][rr*2+1] + btg[c+1]);
                hv[mi][nj][rr*2]   = g0*nv.x + (1.f-g0)*hh.x;
                hv[mi][nj][rr*2+1] = g1*nv.y + (1.f-g1)*hh.y;
            }
        }
    __syncthreads();

    // ---- phase 2: gated fusion (hn1@Ga + h@Gb) ----
    stage_W(sb, K3_W, pGa, tid);
    stage_A_r(smc, K3_A1, hv, lid, wm, wn, (const float*)0, 0, 0);
    asm volatile("cp.async.wait_group 0;");
    __syncthreads();
    ZERO_ACC(acc);
    gemm_tile(sb, K3_A1, K3_W, lid, wm, wn, acc);
    __syncthreads();
    stage_W(sb, K3_W, pGb, tid);
    stage_A_g(smc, K3_A1, h, row0, M, tid);     // A1 <- h
    asm volatile("cp.async.wait_group 0;");
    __syncthreads();
    gemm_tile(sb, K3_A1, K3_W, lid, wm, wn, acc);
    #pragma unroll
    for (int mi = 0; mi < 2; mi++)
        #pragma unroll
        for (int rr = 0; rr < 2; rr++) {
            int row = wm*32 + mi*16 + rr*8 + (lid >> 2);
            #pragma unroll
            for (int nj = 0; nj < 4; nj++) {
                int c = wn*32 + nj*8 + (lid & 3)*2;
                float2 hh = readA2(smc, K3_A1, row, c);   // h
                float g0 = sigf(acc[mi][nj][rr*2]   + bga[c]);
                float g1 = sigf(acc[mi][nj][rr*2+1] + bga[c+1]);
                hv[mi][nj][rr*2]   = g0*hv[mi][nj][rr*2]   + (1.f-g0)*hh.x;
                hv[mi][nj][rr*2+1] = g1*hv[mi][nj][rr*2+1] + (1.f-g1)*hh.y;
            }
        }
    __syncthreads();

    // ---- phase 3: tdiff  (stage hn2 - h; h read from gmem) ----
    stage_W(sb, K3_W, pTd, tid);
    stage_A_r(smc, K3_A1, hv, lid, wm, wn, h, row0, M);
    asm volatile("cp.async.wait_group 0;");
    __syncthreads();
    ZERO_ACC(acc);
    gemm_tile(sb, K3_A1, K3_W, lid, wm, wn, acc);
    #pragma unroll
    for (int mi = 0; mi < 2; mi++)
        #pragma unroll
        for (int rr = 0; rr < 2; rr++) {
            int gr = row0 + wm*32 + mi*16 + rr*8 + (lid >> 2);
            bool rv = (gr < M);
            #pragma unroll
            for (int nj = 0; nj < 4; nj++) {
                int c = wn*32 + nj*8 + (lid & 3)*2;
                float y0 = fmaxf(acc[mi][nj][rr*2]   + btd[c],   0.f);
                float y1 = fmaxf(acc[mi][nj][rr*2+1] + btd[c+1], 0.f);
                hv[mi][nj][rr*2]   += y0;
                hv[mi][nj][rr*2+1] += y1;
                if (rv) *(float2*)(hout + (size_t)gr*128 + c) =
                            make_float2(hv[mi][nj][rr*2], hv[mi][nj][rr*2+1]);
            }
        }

    // ---- phase 4 (optional): HW_next = h_next@Wn1 ----
    if (doHW) {
        __syncthreads();
        stage_W(sb, K3_W, pWn1, tid);
        stage_A_r(smc, K3_A1, hv, lid, wm, wn, (const float*)0, 0, 0);
        asm volatile("cp.async.wait_group 0;");
        __syncthreads();
        ZERO_ACC(acc);
        gemm_tile(sb, K3_A1, K3_W, lid, wm, wn, acc);
        write_plain(HWout, M, row0, lid, wm, wn, acc);
    }
}

// ---------------- host driver ----------------
extern "C" void kernel_launch(void* const* d_in, const int* in_sizes, int n_in,
                              void* d_out, int out_size) {
    const int*   src     = (const int*)d_in[0];
    const int*   dst     = (const int*)d_in[1];
    const int*   ety     = (const int*)d_in[2];
    const float* dyn     = (const float*)d_in[3];
    const float* emb_rel = (const float*)d_in[4];
    const float* Wn1     = (const float*)d_in[5];
    const float* Wl1     = (const float*)d_in[6];
    const float* Wn2     = (const float*)d_in[7];
    const float* Wl2     = (const float*)d_in[8];
    const float* gWx     = (const float*)d_in[9];
    const float* gWh     = (const float*)d_in[10];
    const float* gbx     = (const float*)d_in[11];
    const float* gbh     = (const float*)d_in[12];
    const float* gateW   = (const float*)d_in[13];
    const float* gateb   = (const float*)d_in[14];
    const float* tdW     = (const float*)d_in[15];
    const float* tdb     = (const float*)d_in[16];
    const float* tgW     = (const float*)d_in[17];
    const float* tgb     = (const float*)d_in[18];
    float* out = (float*)d_out;

    float *hA,*hB,*cur,*HW,*agg,*relA,*relB,*R1,*R2,*pre;
    unsigned char* Wp;
    cudaGetSymbolAddress((void**)&hA,  g_hA);
    cudaGetSymbolAddress((void**)&hB,  g_hB);
    cudaGetSymbolAddress((void**)&cur, g_cur);
    cudaGetSymbolAddress((void**)&HW,  g_HW);
    cudaGetSymbolAddress((void**)&agg, g_agg);
    cudaGetSymbolAddress((void**)&relA,g_relA);
    cudaGetSymbolAddress((void**)&relB,g_relB);
    cudaGetSymbolAddress((void**)&R1,  g_R1);
    cudaGetSymbolAddress((void**)&R2,  g_R2);
    cudaGetSymbolAddress((void**)&pre, g_pre);
    cudaGetSymbolAddress((void**)&Wp,  g_Wpack);
    float* deg = agg + (size_t)NENT*HDIM;

    cudaFuncSetAttribute((const void*)plain_gemm,  cudaFuncAttributeMaxDynamicSharedMemorySize, PG_SIZE);
    cudaFuncSetAttribute((const void*)gru_pre,     cudaFuncAttributeMaxDynamicSharedMemorySize, PG_SIZE);
    cudaFuncSetAttribute((const void*)gru_step,    cudaFuncAttributeMaxDynamicSharedMemorySize, PG_SIZE);
    cudaFuncSetAttribute((const void*)gru_combine, cudaFuncAttributeMaxDynamicSharedMemorySize, PG_SIZE);
    cudaFuncSetAttribute((const void*)k2_kernel,   cudaFuncAttributeMaxDynamicSharedMemorySize, PG_SIZE);
    cudaFuncSetAttribute((const void*)k3_kernel,   cudaFuncAttributeMaxDynamicSharedMemorySize, K3_SIZE);

    const unsigned char* pWn1 = Wp + 0*65536;
    const unsigned char* pWl1 = Wp + 1*65536;
    const unsigned char* pWn2 = Wp + 2*65536;
    const unsigned char* pWl2 = Wp + 3*65536;
    const unsigned char* pTg  = Wp + 4*65536;
    const unsigned char* pGa  = Wp + 5*65536;
    const unsigned char* pGb  = Wp + 6*65536;
    const unsigned char* pTd  = Wp + 7*65536;

    const int GB = (NENT + MTILE - 1) / MTILE;       // 1563
    const int EB = ((EE + 1) / 2 * 32 + 255) / 256;  // 2 edges per warp

    pack_kernel<<<17, 256>>>(Wn1, Wl1, Wn2, Wl2, tgW, gateW, tdW, gWx, gWh);
    l2norm_kernel<<<(NENT + 7)/8, 256>>>(dyn, hA, NENT);
    gru_pre<<<24, NTHR, PG_SIZE>>>(emb_rel, Wp, pre);
    plain_gemm<<<GB, NTHR, PG_SIZE>>>(hA, pWn1, HW, NENT);
    // step-0 GRU: rel(0), R1(0), R2(0)
    gru_step<<<48, NTHR, PG_SIZE>>>(emb_rel, Wp, pre);
    gru_combine<<<16, NTHR, PG_SIZE>>>(emb_rel, pre, Wp, gbx, gbh, relA, R1, R2);

    float* relBufs[2] = { relA, relB };
    float* h     = hA;
    float* hnext = hB;

    for (int t = 0; t < TT; t++) {
        const int* sT = src + t*EE;
        const int* dT = dst + t*EE;
        const int* eT = ety + t*EE;
        float* relCur  = relBufs[t & 1];        // rel(t)
        float* relNext = relBufs[(t + 1) & 1];  // rel(t+1)

        // single memset (agg+deg contiguous) immediately before edge1: L2-hot for atomics
        cudaMemsetAsync(agg, 0, ((size_t)NENT*HDIM + NENT)*sizeof(float));

        // layer 1; k2 tail blocks run gru_step(t+1) on rel(t)
        edge_kernel<<<EB, 256>>>(sT, dT, eT, HW, R1, agg, deg, EE, 1);
        k2_kernel<<<GB + 48, NTHR, PG_SIZE>>>(h, pWl1, pWn2, cur, HW, NENT, agg, deg,
                                              relCur, Wp, pre, GB);

        // layer 2
        cudaMemsetAsync(agg, 0, (size_t)NENT*HDIM*sizeof(float));
        edge_kernel<<<EB, 256>>>(sT, dT, eT, HW, R2, agg, deg, EE, 0);

        // k3 tail blocks run gru_combine(t+1): rel(t+1), R1(t+1), R2(t+1)
        float* target = (t == TT-1) ? out : hnext;
        k3_kernel<<<GB + 16, NTHR, K3_SIZE>>>(cur, h, pWl2, pTg, pGa, pGb, pTd, pWn1,
                                              tgb, gateb, tdb, agg, deg,
                                              target, HW, NENT, (t < TT-1) ? 1 : 0,
                                              relCur, pre, Wp, gbx, gbh,
                                              relNext, R1, R2, GB);

        if (t < TT-1) { float* tmp = h; h = hnext; hnext = tmp; }
    }
}